// round 1
// baseline (speedup 1.0000x reference)
#include <cuda_runtime.h>

// Problem constants
#define NTOK 32768          // 32*1024 tokens
#define KC   1024           // codes
#define DD   256            // code dim
#define BM   16             // rows per CTA in main kernel
#define TINV 10.0f          // 1/SOFTMAX_TEMP

// ---- output layout (flattened tuple order) ----
// z_q_st[32,1024,256], codes[32,1024], loss, perplexity, entropy,
// soft_assign[32,1024,1024], new_embed[1024,256], new_cluster_size[1024],
// new_embed_avg[1024,256]
static const long OFF_ZQ    = 0;
static const long OFF_CODES = 8388608;
static const long OFF_LOSS  = 8421376;
static const long OFF_PERP  = 8421377;
static const long OFF_ENT   = 8421378;
static const long OFF_SOFT  = 8421379;
static const long OFF_NEMB  = 41975811;
static const long OFF_NCS   = 42237955;
static const long OFF_NEA   = 42238979;

// ---- device scratch (no dynamic allocation allowed) ----
__device__ float g_e2[KC];
__device__ float g_counts[KC];
__device__ float g_esum[KC * DD];
__device__ float g_loss;

// ---------------------------------------------------------------------------
__global__ void zero_k() {
    int i = blockIdx.x * 256 + threadIdx.x;
    if (i < KC * DD) g_esum[i] = 0.0f;
    if (i < KC)      g_counts[i] = 0.0f;
    if (i == 0)      g_loss = 0.0f;
}

// e2[k] = sum_d embed[k,d]^2   (one warp per code row)
__global__ void e2_k(const float* __restrict__ embed) {
    int w    = (blockIdx.x * 256 + threadIdx.x) >> 5;
    int lane = threadIdx.x & 31;
    if (w >= KC) return;
    const float4* row = (const float4*)(embed + (size_t)w * DD);
    float s = 0.0f;
#pragma unroll
    for (int j = 0; j < 2; j++) {
        float4 v = row[lane + 32 * j];
        s += v.x * v.x + v.y * v.y + v.z * v.z + v.w * v.w;
    }
#pragma unroll
    for (int o = 16; o; o >>= 1) s += __shfl_xor_sync(0xffffffffu, s, o);
    if (lane == 0) g_e2[w] = s;
}

// ---------------------------------------------------------------------------
// Main kernel: BM z-rows x all 1024 codes per CTA.
// Phase 1: register-tiled dot products (each thread: 16 rows x 4 codes).
// Phase 2: per-row (one warp): argmin, softmax, writes, EMA atomics.
extern __shared__ float smem[];

__global__ __launch_bounds__(256, 2)
void vq_main(const float* __restrict__ z,
             const float* __restrict__ embed,
             float* __restrict__ out) {
    float* zs = smem;                 // [BM][DD]   16 KB
    float* sd = smem + BM * DD;       // [BM][KC]   64 KB

    int tid  = threadIdx.x;
    int row0 = blockIdx.x * BM;

    // load z tile (4096 floats = 1024 float4)
    {
        const float4* src = (const float4*)(z + (size_t)row0 * DD);
        float4*       dst = (float4*)zs;
#pragma unroll
        for (int i = 0; i < 4; i++) dst[tid + 256 * i] = src[tid + 256 * i];
    }
    __syncthreads();

    int c0 = tid * 4;
    const float4* ep0 = (const float4*)(embed + (size_t)(c0 + 0) * DD);
    const float4* ep1 = (const float4*)(embed + (size_t)(c0 + 1) * DD);
    const float4* ep2 = (const float4*)(embed + (size_t)(c0 + 2) * DD);
    const float4* ep3 = (const float4*)(embed + (size_t)(c0 + 3) * DD);

    float acc[BM][4];
#pragma unroll
    for (int r = 0; r < BM; r++)
#pragma unroll
        for (int c = 0; c < 4; c++) acc[r][c] = 0.0f;

    float4 e0 = ep0[0], e1 = ep1[0], e2 = ep2[0], e3 = ep3[0];
#pragma unroll 1
    for (int j = 0; j < DD / 4; j++) {
        float4 n0, n1, n2, n3;
        if (j + 1 < DD / 4) { n0 = ep0[j + 1]; n1 = ep1[j + 1];
                              n2 = ep2[j + 1]; n3 = ep3[j + 1]; }
        else                { n0 = e0; n1 = e1; n2 = e2; n3 = e3; }
#pragma unroll
        for (int r = 0; r < BM; r++) {
            float4 zv = ((const float4*)(zs + r * DD))[j];  // warp-broadcast LDS
            acc[r][0] += zv.x * e0.x + zv.y * e0.y + zv.z * e0.z + zv.w * e0.w;
            acc[r][1] += zv.x * e1.x + zv.y * e1.y + zv.z * e1.z + zv.w * e1.w;
            acc[r][2] += zv.x * e2.x + zv.y * e2.y + zv.z * e2.z + zv.w * e2.w;
            acc[r][3] += zv.x * e3.x + zv.y * e3.y + zv.z * e3.z + zv.w * e3.w;
        }
        e0 = n0; e1 = n1; e2 = n2; e3 = n3;
    }

    // dist surrogate s = e2 - 2*dot  (||z||^2 cancels in argmin & softmax)
    float q0 = g_e2[c0], q1 = g_e2[c0 + 1], q2 = g_e2[c0 + 2], q3 = g_e2[c0 + 3];
#pragma unroll
    for (int r = 0; r < BM; r++) {
        float4 s;
        s.x = q0 - 2.0f * acc[r][0];
        s.y = q1 - 2.0f * acc[r][1];
        s.z = q2 - 2.0f * acc[r][2];
        s.w = q3 - 2.0f * acc[r][3];
        *((float4*)(sd + r * KC + c0)) = s;
    }
    __syncthreads();

    // ---- per-row reduction: one warp per row (8 warps, 2 rows each) ----
    int lane = tid & 31, w = tid >> 5;
#pragma unroll 1
    for (int rr = 0; rr < 2; rr++) {
        int r    = w + rr * 8;
        int grow = row0 + r;
        float* row = sd + r * KC;

        // min / argmin (tie-break: smallest index, matching jnp.argmin)
        float mn = 3.4e38f; int arg = 0;
#pragma unroll
        for (int j = 0; j < 32; j++) {
            float v = row[j * 32 + lane];
            if (v < mn) { mn = v; arg = j * 32 + lane; }
        }
#pragma unroll
        for (int o = 16; o; o >>= 1) {
            float ov = __shfl_xor_sync(0xffffffffu, mn, o);
            int   oa = __shfl_xor_sync(0xffffffffu, arg, o);
            if (ov < mn || (ov == mn && oa < arg)) { mn = ov; arg = oa; }
        }

        // exp + sum (stable: subtract row max of logits = -min dist)
        float sum = 0.0f;
#pragma unroll
        for (int j = 0; j < 32; j++) {
            float v = __expf((mn - row[j * 32 + lane]) * TINV);
            row[j * 32 + lane] = v;
            sum += v;
        }
#pragma unroll
        for (int o = 16; o; o >>= 1) sum += __shfl_xor_sync(0xffffffffu, sum, o);
        float inv = 1.0f / sum;

        float* soft = out + OFF_SOFT + (long)grow * KC;
#pragma unroll
        for (int j = 0; j < 32; j++)
            soft[j * 32 + lane] = row[j * 32 + lane] * inv;

        // z_q (= z_q_st numerically), commitment-loss partial, EMA sums
        int code = arg;
        const float* er = embed + (size_t)code * DD;
        float* zq = out + OFF_ZQ + (long)grow * DD;
        float lp = 0.0f;
#pragma unroll
        for (int j = 0; j < 8; j++) {
            int d    = j * 32 + lane;
            float ev = er[d];
            float zv = zs[r * DD + d];
            zq[d] = ev;
            float df = zv - ev;
            lp += df * df;
            atomicAdd(&g_esum[code * DD + d], zv);
        }
#pragma unroll
        for (int o = 16; o; o >>= 1) lp += __shfl_xor_sync(0xffffffffu, lp, o);
        if (lane == 0) {
            out[OFF_CODES + grow] = (float)code;
            atomicAdd(&g_counts[code], 1.0f);
            atomicAdd(&g_loss, lp);
        }
    }
}

// ---------------------------------------------------------------------------
// Finalize: EMA buffers, normalized embed, entropy/perplexity, loss mean.
__global__ void fin_k(const float* __restrict__ cs,
                      const float* __restrict__ ea,
                      float* __restrict__ out) {
    __shared__ float red[1024];
    __shared__ float csn_s[1024];
    int k = threadIdx.x;

    float cnt = g_counts[k];
    float ncs = 0.99f * cs[k] + 0.01f * cnt;
    out[OFF_NCS + k] = ncs;

    red[k] = ncs;
    __syncthreads();
    for (int s = 512; s; s >>= 1) { if (k < s) red[k] += red[k + s]; __syncthreads(); }
    float n = red[0];
    __syncthreads();

    float csn = (ncs + 1e-5f) / (n + 1024.0f * 1e-5f) * n;
    csn_s[k] = csn;

    float p = cnt * (1.0f / 32768.0f);
    red[k] = -p * logf(p + 1e-10f);
    __syncthreads();
    for (int s = 512; s; s >>= 1) { if (k < s) red[k] += red[k + s]; __syncthreads(); }

    if (k == 0) {
        float ent = red[0];
        out[OFF_ENT]  = ent;
        out[OFF_PERP] = expf(ent);
        out[OFF_LOSS] = g_loss * (1.0f / (32768.0f * 256.0f));
    }

    // new_embed_avg and new_embed (coalesced over flattened [K*D])
    for (int idx = k; idx < KC * DD; idx += 1024) {
        float v = 0.99f * ea[idx] + 0.01f * g_esum[idx];
        out[OFF_NEA  + idx] = v;
        out[OFF_NEMB + idx] = v / csn_s[idx >> 8];
    }
}

// ---------------------------------------------------------------------------
extern "C" void kernel_launch(void* const* d_in, const int* in_sizes, int n_in,
                              void* d_out, int out_size) {
    const float* z     = (const float*)d_in[0];
    const float* embed = (const float*)d_in[1];
    const float* cs    = (const float*)d_in[2];
    const float* ea    = (const float*)d_in[3];
    float* out = (float*)d_out;

    const int smem_bytes = (BM * DD + BM * KC) * 4;   // 81920
    cudaFuncSetAttribute(vq_main, cudaFuncAttributeMaxDynamicSharedMemorySize,
                         smem_bytes);

    zero_k<<<1024, 256>>>();
    e2_k<<<128, 256>>>(embed);
    vq_main<<<NTOK / BM, 256, smem_bytes>>>(z, embed, out);
    fin_k<<<1, 1024>>>(cs, ea, out);
}